// round 5
// baseline (speedup 1.0000x reference)
#include <cuda_runtime.h>
#include <cuda_bf16.h>
#include <stdint.h>

#define N_NODES 100000
#define N_EDGES 2000000
#define PER 12
#define H 128
#define TILE_M 128
#define NT (N_EDGES / TILE_M)   // 15625
#define GRID 148
#define NTHREADS 384            // 8 consumer warps + 4 producer warps

// ---------------- device scratch (allocation-free rule) ----------------
__device__ float g_P[N_NODES * H];          // node_embs @ W1[:12] + b1
__device__ float g_Q[N_NODES * H];          // node_embs @ W1[12:]
__device__ unsigned char g_Bth[H * H * 2];  // W2^T bf16 hi, swizzled [n][k]
__device__ unsigned char g_Btl[H * H * 2];  // W2^T bf16 lo
__device__ double g_sum;

// ---------------- helpers ----------------
__device__ __forceinline__ uint32_t smem_to_u32(const void* p) {
    uint32_t a;
    asm("{ .reg .u64 t; cvta.to.shared.u64 t, %1; cvt.u32.u64 %0, t; }" : "=r"(a) : "l"(p));
    return a;
}
#define MBARRIER_INIT(addr, cnt) \
    asm volatile("mbarrier.init.shared.b64 [%0], %1;" :: "r"((uint32_t)(addr)), "r"((uint32_t)(cnt)) : "memory")
#define MBARRIER_ARRIVE(addr) \
    asm volatile("mbarrier.arrive.shared.b64 _, [%0];" :: "r"((uint32_t)(addr)) : "memory")
#define MBARRIER_WAIT_PARITY(addr, par) do { \
    uint32_t _m = (uint32_t)(addr), _p = (uint32_t)(par), _d; \
    asm volatile("{\n\t.reg .pred p;\n\tmbarrier.try_wait.parity.acquire.cta.shared::cta.b64 p, [%1], %2;\n\tselp.b32 %0, 1, 0, p;\n\t}" \
        : "=r"(_d) : "r"(_m), "r"(_p) : "memory"); \
    if (!_d) { \
        asm volatile("{\n\t.reg .pred P1;\n\tWL_%=:\n\tmbarrier.try_wait.parity.acquire.cta.shared::cta.b64 P1, [%0], %1, 0x989680;\n\t@P1 bra.uni WD_%=;\n\tbra.uni WL_%=;\n\tWD_%=:\n\t}" \
            :: "r"(_m), "r"(_p) : "memory"); \
    } } while (0)
#define NAMED_BAR(id, n) asm volatile("bar.sync %0, %1;" :: "r"(id), "r"(n) : "memory")
// pack: lo16 = bf16(x), hi16 = bf16(y)
#define PACK_BF2(d, x, y) \
    asm("cvt.rn.bf16x2.f32 %0, %1, %2;" : "=r"(d) : "f"(y), "f"(x))
#define LDSM_X4(r0, r1, r2, r3, addr) \
    asm volatile("ldmatrix.sync.aligned.m8n8.x4.shared.b16 {%0,%1,%2,%3}, [%4];" \
        : "=r"(r0), "=r"(r1), "=r"(r2), "=r"(r3) : "r"(addr))
#define MMA16816(d, a0, a1, a2, a3, b0, b1) \
    asm volatile("mma.sync.aligned.m16n8k16.row.col.f32.bf16.bf16.f32 " \
        "{%0,%1,%2,%3}, {%4,%5,%6,%7}, {%8,%9}, {%0,%1,%2,%3};" \
        : "+f"((d)[0]), "+f"((d)[1]), "+f"((d)[2]), "+f"((d)[3]) \
        : "r"(a0), "r"(a1), "r"(a2), "r"(a3), "r"(b0), "r"(b1))

// ---------------- SMEM layout ----------------
#define SO_MBAR 0        // full0,full1,free0,free1 (8B each)
#define SO_EP   1024     // 128 x float4 {b2, Wv+Wa, Wa, 0}
#define SO_PART 3072     // 128 rows x 8 warps x float2 = 8KB
#define SO_B    11264    // Bt hi 32KB, lo 32KB
#define SO_A    76800    // + s*65536 : hi 32KB, lo +32768
#define SMEM_TOTAL 207872

// ---------------------------------------------------------------------------
// Kernel A: P = E@W1_top + b1 ; Q = E@W1_bot. One warp per node.
// ---------------------------------------------------------------------------
__global__ void precompute_kernel(const float* __restrict__ E,
                                  const float* __restrict__ W1,
                                  const float* __restrict__ b1) {
    if (blockIdx.x == 0 && threadIdx.x == 0) g_sum = 0.0;
    int warp = (blockIdx.x * blockDim.x + threadIdx.x) >> 5;
    int lane = threadIdx.x & 31;
    if (warp >= N_NODES) return;
    const float* e = E + warp * PER;
    float ek[PER];
#pragma unroll
    for (int k = 0; k < PER; ++k) ek[k] = __ldg(e + k);
    int j = lane << 2;
    float4 p = *(const float4*)(b1 + j);
    float4 q = make_float4(0.f, 0.f, 0.f, 0.f);
#pragma unroll
    for (int k = 0; k < PER; ++k) {
        float4 wa = *(const float4*)(W1 + k * H + j);
        float4 wb = *(const float4*)(W1 + (k + PER) * H + j);
        p.x += ek[k] * wa.x; p.y += ek[k] * wa.y; p.z += ek[k] * wa.z; p.w += ek[k] * wa.w;
        q.x += ek[k] * wb.x; q.y += ek[k] * wb.y; q.z += ek[k] * wb.z; q.w += ek[k] * wb.w;
    }
    *(float4*)(g_P + warp * H + j) = p;
    *(float4*)(g_Q + warp * H + j) = q;
}

// ---------------------------------------------------------------------------
// Kernel A2: W2^T -> bf16 hi/lo, swizzled [n][k]: byte = n*256 +
//            (((k>>3) ^ (n&7))<<4) + (k&7)*2
// ---------------------------------------------------------------------------
__global__ void prep_w2_kernel(const float* __restrict__ W2) {
    int i = blockIdx.x * blockDim.x + threadIdx.x;
    if (i >= H * H) return;
    int n = i >> 7, k = i & 127;
    float x = W2[k * H + n];
    __nv_bfloat16 hb16 = __float2bfloat16(x);
    unsigned short hb = *(unsigned short*)&hb16;
    float hf = __uint_as_float((uint32_t)hb << 16);
    __nv_bfloat16 lb16 = __float2bfloat16(x - hf);
    unsigned short lb = *(unsigned short*)&lb16;
    uint32_t off = ((uint32_t)n << 8) + ((((uint32_t)(k >> 3)) ^ (uint32_t)(n & 7)) << 4)
                 + (((uint32_t)k & 7u) << 1);
    *(unsigned short*)(g_Bth + off) = hb;
    *(unsigned short*)(g_Btl + off) = lb;
}

// ---------------------------------------------------------------------------
// Kernel B: warp-specialized HMMA pipeline, 2 consumer warps per SMSP.
//   warps 8-11 (producers): per-thread edge gather (R3 pattern),
//       bf16 hi/lo split into double-buffered swizzled SMEM A.
//   warps 0-7 (consumers): each owns n-slice of 16; 384 mma.m16n8k16 per tile;
//       in-register dueling-head epilogue.
// ---------------------------------------------------------------------------
extern __shared__ unsigned char smx[];

__global__ void __launch_bounds__(NTHREADS, 1)
edge_kernel(const int* __restrict__ src, const int* __restrict__ dst,
            const float* __restrict__ b2, const float* __restrict__ Wv,
            const float* __restrict__ bv, const float* __restrict__ Wa,
            float* __restrict__ out) {
    uint32_t sb = smem_to_u32(smx);
    int tid = threadIdx.x, wid = tid >> 5, lane = tid & 31;

    if (tid == 0) {
        MBARRIER_INIT(sb + SO_MBAR + 0, 128);   // full[0] (producer arrivals)
        MBARRIER_INIT(sb + SO_MBAR + 8, 128);   // full[1]
        MBARRIER_INIT(sb + SO_MBAR + 16, 256);  // free[0] (consumer arrivals)
        MBARRIER_INIT(sb + SO_MBAR + 24, 256);  // free[1]
    }
    if (tid < H) {
        float wa = Wa[tid];
        ((float4*)(smx + SO_EP))[tid] = make_float4(b2[tid], Wv[tid] + wa, wa, 0.f);
    }
    {   // stage pre-swizzled W2^T hi/lo into SMEM
        const int4* s1 = (const int4*)g_Bth;
        const int4* s2 = (const int4*)g_Btl;
        int4* d1 = (int4*)(smx + SO_B);
        int4* d2 = (int4*)(smx + SO_B + 32768);
        for (int i = tid; i < 2048; i += NTHREADS) { d1[i] = s1[i]; d2[i] = s2[i]; }
    }
    __syncthreads();
    float bv0 = __ldg(bv);
    float asum = 0.f;

    if (wid >= 8) {
        // ======================= PRODUCERS (R3 per-thread gather) =========
        int r = tid - 256;                 // row 0..127
        uint32_t xr = (uint32_t)(r & 7);
        int s = 0, ph = 1;
        for (int t = blockIdx.x; t < NT; t += GRID) {
            MBARRIER_WAIT_PARITY(sb + SO_MBAR + 16 + s * 8, ph);   // buf free
            int si = __ldg(src + t * TILE_M + r);
            int di = __ldg(dst + t * TILE_M + r);
            const float4* Pp = (const float4*)(g_P + si * H);
            const float4* Qp = (const float4*)(g_Q + di * H);
            uint32_t ahb = sb + SO_A + (uint32_t)s * 65536u + ((uint32_t)r << 8);
#pragma unroll 4
            for (int c = 0; c < 16; ++c) {   // 8 cols per chunk
                float4 pa = Pp[2 * c], pb = Pp[2 * c + 1];
                float4 qa = Qp[2 * c], qb = Qp[2 * c + 1];
                float v0 = fmaxf(pa.x + qa.x, 0.f), v1 = fmaxf(pa.y + qa.y, 0.f);
                float v2 = fmaxf(pa.z + qa.z, 0.f), v3 = fmaxf(pa.w + qa.w, 0.f);
                float v4 = fmaxf(pb.x + qb.x, 0.f), v5 = fmaxf(pb.y + qb.y, 0.f);
                float v6 = fmaxf(pb.z + qb.z, 0.f), v7 = fmaxf(pb.w + qb.w, 0.f);
                uint32_t h0, h1, h2, h3, l0, l1, l2, l3;
                PACK_BF2(h0, v0, v1); PACK_BF2(h1, v2, v3);
                PACK_BF2(h2, v4, v5); PACK_BF2(h3, v6, v7);
                float r0 = v0 - __uint_as_float(h0 << 16);
                float r1 = v1 - __uint_as_float(h0 & 0xffff0000u);
                float r2 = v2 - __uint_as_float(h1 << 16);
                float r3 = v3 - __uint_as_float(h1 & 0xffff0000u);
                float r4 = v4 - __uint_as_float(h2 << 16);
                float r5 = v5 - __uint_as_float(h2 & 0xffff0000u);
                float r6 = v6 - __uint_as_float(h3 << 16);
                float r7 = v7 - __uint_as_float(h3 & 0xffff0000u);
                PACK_BF2(l0, r0, r1); PACK_BF2(l1, r2, r3);
                PACK_BF2(l2, r4, r5); PACK_BF2(l3, r6, r7);
                uint32_t off = (((uint32_t)c ^ xr) << 4);
                asm volatile("st.shared.v4.b32 [%0], {%1,%2,%3,%4};"
                             :: "r"(ahb + off), "r"(h0), "r"(h1), "r"(h2), "r"(h3) : "memory");
                asm volatile("st.shared.v4.b32 [%0], {%1,%2,%3,%4};"
                             :: "r"(ahb + off + 32768u), "r"(l0), "r"(l1), "r"(l2), "r"(l3) : "memory");
            }
            MBARRIER_ARRIVE(sb + SO_MBAR + s * 8);   // buf full
            s ^= 1; if (!s) ph ^= 1;
        }
    } else {
        // ======================= CONSUMERS (8 warps, N=16 slice each) =====
        int w = wid;                 // n-slice [16w, 16w+16)
        int g = lane >> 3, lr = lane & 7;
        uint32_t xr = (uint32_t)lr;
        uint32_t a_rowoff = ((uint32_t)(((g & 1) << 3) + lr)) << 8;
        uint32_t a_cs = (uint32_t)(g >> 1);
        // B: mat0=(n0-7,k0-7) mat1=(n8-15,k0-7) mat2=(n0-7,k8-15) mat3=(n8-15,k8-15)
        uint32_t b_row = (uint32_t)(16 * w + ((g & 1) << 3) + lr);
        uint32_t b_cs = (uint32_t)(g >> 1);
        uint32_t Bbase = sb + SO_B + (b_row << 8);
        const float4* ep = (const float4*)(smx + SO_EP);
        float2* part = (float2*)(smx + SO_PART);
        int c0base = 16 * w + 2 * (lane & 3);

        int s = 0, ph = 0;
        for (int t = blockIdx.x; t < NT; t += GRID) {
            MBARRIER_WAIT_PARITY(sb + SO_MBAR + s * 8, ph);   // buf full
            uint32_t Ah = sb + SO_A + (uint32_t)s * 65536u + a_rowoff;
            float acc[8][8];
#pragma unroll
            for (int i = 0; i < 8; ++i)
#pragma unroll
                for (int j = 0; j < 8; ++j) acc[i][j] = 0.f;
#pragma unroll
            for (int ks = 0; ks < 8; ++ks) {
                uint32_t bch = (((uint32_t)(2 * ks) + b_cs) ^ xr) << 4;
                uint32_t bh0, bh1, bh2, bh3, bl0, bl1, bl2, bl3;
                LDSM_X4(bh0, bh1, bh2, bh3, Bbase + bch);
                LDSM_X4(bl0, bl1, bl2, bl3, Bbase + bch + 32768u);
                uint32_t ach = (((uint32_t)(2 * ks) + a_cs) ^ xr) << 4;
#pragma unroll
                for (int mb = 0; mb < 8; ++mb) {
                    uint32_t aa = Ah + ((uint32_t)mb << 12) + ach;
                    uint32_t a0, a1, a2, a3, c0, c1, c2, c3;
                    LDSM_X4(a0, a1, a2, a3, aa);
                    LDSM_X4(c0, c1, c2, c3, aa + 32768u);
                    // n-block0 uses (mat0, mat2); n-block1 uses (mat1, mat3)
                    MMA16816(acc[mb] + 0, a0, a1, a2, a3, bh0, bh2);
                    MMA16816(acc[mb] + 4, a0, a1, a2, a3, bh1, bh3);
                    MMA16816(acc[mb] + 0, a0, a1, a2, a3, bl0, bl2);
                    MMA16816(acc[mb] + 4, a0, a1, a2, a3, bl1, bl3);
                    MMA16816(acc[mb] + 0, c0, c1, c2, c3, bh0, bh2);
                    MMA16816(acc[mb] + 4, c0, c1, c2, c3, bh1, bh3);
                }
            }
            MBARRIER_ARRIVE(sb + SO_MBAR + 16 + s * 8);   // buf free

            // ---- epilogue: relu + dueling heads, all in registers ----
            // col layout per lane: c0, c0+1 (n-block0), c0+8, c0+9 (n-block1)
            float4 ec0 = ep[c0base], ec1 = ep[c0base + 1];
            float4 ec2 = ep[c0base + 8], ec3 = ep[c0base + 9];
#pragma unroll
            for (int mb = 0; mb < 8; ++mb) {
                float qp0 = 0.f, av0 = 0.f, qp1 = 0.f, av1 = 0.f;
                float h;
                h = fmaxf(acc[mb][0] + ec0.x, 0.f); qp0 += h * ec0.y; av0 += h * ec0.z;
                h = fmaxf(acc[mb][1] + ec1.x, 0.f); qp0 += h * ec1.y; av0 += h * ec1.z;
                h = fmaxf(acc[mb][4] + ec2.x, 0.f); qp0 += h * ec2.y; av0 += h * ec2.z;
                h = fmaxf(acc[mb][5] + ec3.x, 0.f); qp0 += h * ec3.y; av0 += h * ec3.z;
                h = fmaxf(acc[mb][2] + ec0.x, 0.f); qp1 += h * ec0.y; av1 += h * ec0.z;
                h = fmaxf(acc[mb][3] + ec1.x, 0.f); qp1 += h * ec1.y; av1 += h * ec1.z;
                h = fmaxf(acc[mb][6] + ec2.x, 0.f); qp1 += h * ec2.y; av1 += h * ec2.z;
                h = fmaxf(acc[mb][7] + ec3.x, 0.f); qp1 += h * ec3.y; av1 += h * ec3.z;
                qp0 += __shfl_xor_sync(0xffffffffu, qp0, 1); qp0 += __shfl_xor_sync(0xffffffffu, qp0, 2);
                av0 += __shfl_xor_sync(0xffffffffu, av0, 1); av0 += __shfl_xor_sync(0xffffffffu, av0, 2);
                qp1 += __shfl_xor_sync(0xffffffffu, qp1, 1); qp1 += __shfl_xor_sync(0xffffffffu, qp1, 2);
                av1 += __shfl_xor_sync(0xffffffffu, av1, 1); av1 += __shfl_xor_sync(0xffffffffu, av1, 2);
                if ((lane & 3) == 0) {
                    int r0 = 16 * mb + (lane >> 2);
                    part[r0 * 8 + w] = make_float2(qp0, av0);
                    part[(r0 + 8) * 8 + w] = make_float2(qp1, av1);
                }
            }
            NAMED_BAR(1, 256);
            if (tid < 128) {
                int row = tid;
                const float4* pp = (const float4*)(smx + SO_PART) + row * 4;
                float4 u0 = pp[0], u1 = pp[1], u2 = pp[2], u3 = pp[3];
                out[t * TILE_M + row] = u0.x + u0.z + u1.x + u1.z
                                      + u2.x + u2.z + u3.x + u3.z + bv0;
                asum += u0.y + u0.w + u1.y + u1.w + u2.y + u2.w + u3.y + u3.w;
            }
            NAMED_BAR(1, 256);
            s ^= 1; if (!s) ph ^= 1;
        }
    }

    __syncthreads();
#pragma unroll
    for (int o = 16; o; o >>= 1) asum += __shfl_xor_sync(0xffffffffu, asum, o);
    float* red = (float*)(smx + SO_PART);
    if (lane == 0) red[wid] = asum;
    __syncthreads();
    if (tid == 0) {
        float sf = 0.f;
#pragma unroll
        for (int i = 0; i < 12; ++i) sf += red[i];
        atomicAdd(&g_sum, (double)sf);
    }
}

// ---------------------------------------------------------------------------
__global__ void finalize_kernel(float* __restrict__ out) {
    int i = blockIdx.x * blockDim.x + threadIdx.x;
    if (i < N_EDGES) {
        float mean = (float)(g_sum * (1.0 / (double)N_EDGES));
        out[i] -= mean;
    }
}

// ---------------------------------------------------------------------------
extern "C" void kernel_launch(void* const* d_in, const int* in_sizes, int n_in,
                              void* d_out, int out_size) {
    const float* node_embs = (const float*)d_in[0];
    const int*   src       = (const int*)d_in[1];
    const int*   dst       = (const int*)d_in[2];
    const float* W1        = (const float*)d_in[3];
    const float* b1        = (const float*)d_in[4];
    const float* W2        = (const float*)d_in[5];
    const float* b2        = (const float*)d_in[6];
    const float* Wv        = (const float*)d_in[7];
    const float* bv        = (const float*)d_in[8];
    const float* Wa        = (const float*)d_in[9];
    // ba (d_in[10]) cancels algebraically
    float* out = (float*)d_out;

    precompute_kernel<<<(N_NODES * 32 + 255) / 256, 256>>>(node_embs, W1, b1);
    prep_w2_kernel<<<(H * H + 255) / 256, 256>>>(W2);

    cudaFuncSetAttribute(edge_kernel,
                         cudaFuncAttributeMaxDynamicSharedMemorySize, SMEM_TOTAL);
    edge_kernel<<<GRID, NTHREADS, SMEM_TOTAL>>>(src, dst, b2, Wv, bv, Wa, out);

    finalize_kernel<<<(N_EDGES + 255) / 256, 256>>>(out);
}

// round 6
// speedup vs baseline: 1.7250x; 1.7250x over previous
#include <cuda_runtime.h>
#include <cuda_bf16.h>
#include <stdint.h>

#define N_NODES 100000
#define N_EDGES 2000000
#define PER 12
#define H 128
#define TILE_M 128
#define NT (N_EDGES / TILE_M)   // 15625
#define GRID 148
#define NTHREADS 384            // warps 0-7 consumers, 8-11 producers

#define SCALE_A (5.0f / 32512.0f)
#define INV_A   (32512.0f / 5.0f)

// ---------------- device scratch (allocation-free rule) ----------------
__device__ float g_P[N_NODES * H];       // node_embs @ W1[:12] + b1
__device__ float g_Q[N_NODES * H];       // node_embs @ W1[12:]
__device__ unsigned char g_B[32768];     // W2^T int8: hi plane 16KB, lo plane 16KB (swizzled)
__device__ float g_C1[H];                // per-col scale: S_A * t_n * 65536 / 32512
__device__ double g_sum;

// ---------------- helpers ----------------
__device__ __forceinline__ uint32_t smem_to_u32(const void* p) {
    uint32_t a;
    asm("{ .reg .u64 t; cvta.to.shared.u64 t, %1; cvt.u32.u64 %0, t; }" : "=r"(a) : "l"(p));
    return a;
}
#define MBARRIER_INIT(addr, cnt) \
    asm volatile("mbarrier.init.shared.b64 [%0], %1;" :: "r"((uint32_t)(addr)), "r"((uint32_t)(cnt)) : "memory")
#define MBARRIER_ARRIVE(addr) \
    asm volatile("mbarrier.arrive.shared.b64 _, [%0];" :: "r"((uint32_t)(addr)) : "memory")
#define MBARRIER_WAIT_PARITY(addr, par) do { \
    uint32_t _m = (uint32_t)(addr), _p = (uint32_t)(par), _d; \
    asm volatile("{\n\t.reg .pred p;\n\tmbarrier.try_wait.parity.acquire.cta.shared::cta.b64 p, [%1], %2;\n\tselp.b32 %0, 1, 0, p;\n\t}" \
        : "=r"(_d) : "r"(_m), "r"(_p) : "memory"); \
    if (!_d) { \
        asm volatile("{\n\t.reg .pred P1;\n\tWL_%=:\n\tmbarrier.try_wait.parity.acquire.cta.shared::cta.b64 P1, [%0], %1, 0x989680;\n\t@P1 bra.uni WD_%=;\n\tbra.uni WL_%=;\n\tWD_%=:\n\t}" \
            :: "r"(_m), "r"(_p) : "memory"); \
    } } while (0)
#define NAMED_BAR(id, n) asm volatile("bar.sync %0, %1;" :: "r"(id), "r"(n) : "memory")
#define LDSM_X4(r0, r1, r2, r3, addr) \
    asm volatile("ldmatrix.sync.aligned.m8n8.x4.shared.b16 {%0,%1,%2,%3}, [%4];" \
        : "=r"(r0), "=r"(r1), "=r"(r2), "=r"(r3) : "r"(addr))
#define MMAS8(d, a0, a1, a2, a3, b0, b1) \
    asm volatile("mma.sync.aligned.m16n8k32.row.col.s32.s8.s8.s32 " \
        "{%0,%1,%2,%3}, {%4,%5,%6,%7}, {%8,%9}, {%0,%1,%2,%3};" \
        : "+r"((d)[0]), "+r"((d)[1]), "+r"((d)[2]), "+r"((d)[3]) \
        : "r"(a0), "r"(a1), "r"(a2), "r"(a3), "r"(b0), "r"(b1))
// pack 4 s32 (already in s8 range) -> 1 u32, byte0 = v0
#define PACK_S8(d, v0, v1, v2, v3) \
    asm("{\n\t.reg .b32 t;\n\tcvt.pack.sat.s8.s32.b32 t, %3, %4, %5;\n\t" \
        "cvt.pack.sat.s8.s32.b32 %0, %1, %2, t;\n\t}" \
        : "=r"(d) : "r"(v1), "r"(v0), "r"(v3), "r"(v2), "r"(0))

// ---------------- SMEM layout (bytes from dynamic base) ----------------
#define SO_MBAR 0        // full0,full1 @0,8 ; free0,free1 @16,24
#define SO_EP   1024     // 128 x float4 {b2, Wv+Wa, Wa, C1}
#define SO_PART 3072     // 128 rows x 4 x float2 = 4KB
#define SO_B    8192     // B hi 16KB @8192, lo @24576
#define SO_A    40960    // stage s @ +s*32768 : hi 16KB, lo +16384
#define SMEM_TOTAL 106496

// ---------------------------------------------------------------------------
// Kernel A: P = E@W1_top + b1 ; Q = E@W1_bot. One warp per node.
// ---------------------------------------------------------------------------
__global__ void precompute_kernel(const float* __restrict__ E,
                                  const float* __restrict__ W1,
                                  const float* __restrict__ b1) {
    if (blockIdx.x == 0 && threadIdx.x == 0) g_sum = 0.0;
    int warp = (blockIdx.x * blockDim.x + threadIdx.x) >> 5;
    int lane = threadIdx.x & 31;
    if (warp >= N_NODES) return;
    const float* e = E + warp * PER;
    float ek[PER];
#pragma unroll
    for (int k = 0; k < PER; ++k) ek[k] = __ldg(e + k);
    int j = lane << 2;
    float4 p = *(const float4*)(b1 + j);
    float4 q = make_float4(0.f, 0.f, 0.f, 0.f);
#pragma unroll
    for (int k = 0; k < PER; ++k) {
        float4 wa = *(const float4*)(W1 + k * H + j);
        float4 wb = *(const float4*)(W1 + (k + PER) * H + j);
        p.x += ek[k] * wa.x; p.y += ek[k] * wa.y; p.z += ek[k] * wa.z; p.w += ek[k] * wa.w;
        q.x += ek[k] * wb.x; q.y += ek[k] * wb.y; q.z += ek[k] * wb.z; q.w += ek[k] * wb.w;
    }
    *(float4*)(g_P + warp * H + j) = p;
    *(float4*)(g_Q + warp * H + j) = q;
}

// ---------------------------------------------------------------------------
// Kernel A2: quantize W2^T per column n: B15 = rni(W2*32512/colmax),
//            split hi/lo int8, store swizzled [n][k] (128B rows).
// swizzle: byte(n,k) = n*128 + (((k>>4) ^ (n&7))<<4) + (k&15)
// ---------------------------------------------------------------------------
__global__ void prep_w2_kernel(const float* __restrict__ W2) {
    __shared__ float red[4];
    int n = blockIdx.x, k = threadIdx.x;
    float w = W2[k * H + n];
    float m = fabsf(w);
#pragma unroll
    for (int o = 16; o; o >>= 1) m = fmaxf(m, __shfl_xor_sync(0xffffffffu, m, o));
    if ((k & 31) == 0) red[k >> 5] = m;
    __syncthreads();
    float t = fmaxf(fmaxf(red[0], red[1]), fmaxf(red[2], red[3]));
    t = fmaxf(t, 1e-20f);
    int B15 = __float2int_rn(w * (32512.0f / t));
    int hi = (B15 + 128) >> 8;
    int lo = B15 - (hi << 8);
    uint32_t addr = ((uint32_t)n << 7) + ((((uint32_t)(k >> 4)) ^ (uint32_t)(n & 7)) << 4)
                  + ((uint32_t)k & 15u);
    g_B[addr] = (unsigned char)(hi & 255);
    g_B[addr + 16384] = (unsigned char)(lo & 255);
    if (k == 0) g_C1[n] = t * (SCALE_A * 65536.0f / 32512.0f);
}

// ---------------------------------------------------------------------------
// Kernel B: warp-specialized int8 HMMA pipeline.
//   warps 8-11 (producers): coalesced gather (4 rows/warp-LDG), fp32 relu add,
//       fixed-scale 15-bit quantize -> int8 hi/lo planes in SMEM (2 stages).
//   warps 0-7 (consumers): 2 m-groups x 4 n-slices; 192 mma.m16n8k32.s8/warp
//       per tile (3 passes: hh, hl+lh); fp32 dueling-head epilogue.
// ---------------------------------------------------------------------------
extern __shared__ unsigned char smx[];

__global__ void __launch_bounds__(NTHREADS, 1)
edge_kernel(const int* __restrict__ src, const int* __restrict__ dst,
            const float* __restrict__ b2, const float* __restrict__ Wv,
            const float* __restrict__ bv, const float* __restrict__ Wa,
            float* __restrict__ out) {
    uint32_t sb = smem_to_u32(smx);
    int tid = threadIdx.x, wid = tid >> 5, lane = tid & 31;

    if (tid == 0) {
        MBARRIER_INIT(sb + SO_MBAR + 0, 128);   // full[0]
        MBARRIER_INIT(sb + SO_MBAR + 8, 128);   // full[1]
        MBARRIER_INIT(sb + SO_MBAR + 16, 256);  // free[0]
        MBARRIER_INIT(sb + SO_MBAR + 24, 256);  // free[1]
    }
    if (tid < H) {
        float wa = Wa[tid];
        ((float4*)(smx + SO_EP))[tid] = make_float4(b2[tid], Wv[tid] + wa, wa, g_C1[tid]);
    }
    {   // stage pre-swizzled int8 W2^T (hi+lo planes) into SMEM
        const int4* s1 = (const int4*)g_B;
        int4* d1 = (int4*)(smx + SO_B);
        for (int i = tid; i < 2048; i += NTHREADS) d1[i] = s1[i];
    }
    __syncthreads();
    float bv0 = __ldg(bv);
    float asum = 0.f;

    if (wid >= 8) {
        // ======================= PRODUCERS =======================
        int wbase = (wid - 8) * 32;
        int rr = lane >> 3;          // row-in-group 0..3
        int cc = lane & 7;           // 16B column chunk owner
        int s = 0, ph = 1;
        for (int t = blockIdx.x; t < NT; t += GRID) {
            int sidx[8], didx[8];
#pragma unroll
            for (int rg = 0; rg < 8; ++rg) {
                sidx[rg] = __ldg(src + t * TILE_M + wbase + rg * 4 + rr);
                didx[rg] = __ldg(dst + t * TILE_M + wbase + rg * 4 + rr);
            }
            MBARRIER_WAIT_PARITY(sb + SO_MBAR + 16 + s * 8, ph);   // buf free
            uint32_t abase = sb + SO_A + (uint32_t)s * 32768u;
#pragma unroll 2
            for (int rg = 0; rg < 8; ++rg) {
                const float* Pp = g_P + sidx[rg] * H;
                const float* Qp = g_Q + didx[rg] * H;
                int row = wbase + rg * 4 + rr;
                uint32_t rowaddr = abase + ((uint32_t)row << 7);
                uint32_t r7 = (uint32_t)(row & 7);
#pragma unroll
                for (int seg = 0; seg < 4; ++seg) {
                    float4 p = *(const float4*)(Pp + seg * 32 + cc * 4);
                    float4 q = *(const float4*)(Qp + seg * 32 + cc * 4);
                    float h0 = fmaxf(p.x + q.x, 0.f), h1 = fmaxf(p.y + q.y, 0.f);
                    float h2 = fmaxf(p.z + q.z, 0.f), h3 = fmaxf(p.w + q.w, 0.f);
                    int a0 = __float2int_rn(h0 * INV_A), a1 = __float2int_rn(h1 * INV_A);
                    int a2 = __float2int_rn(h2 * INV_A), a3 = __float2int_rn(h3 * INV_A);
                    int hi0 = (a0 + 128) >> 8, hi1 = (a1 + 128) >> 8;
                    int hi2 = (a2 + 128) >> 8, hi3 = (a3 + 128) >> 8;
                    int lo0 = a0 - (hi0 << 8), lo1 = a1 - (hi1 << 8);
                    int lo2 = a2 - (hi2 << 8), lo3 = a3 - (hi3 << 8);
                    uint32_t phw, plw;
                    PACK_S8(phw, hi0, hi1, hi2, hi3);
                    PACK_S8(plw, lo0, lo1, lo2, lo3);
                    uint32_t chunk = (uint32_t)(2 * seg) + ((uint32_t)cc >> 2);
                    uint32_t sw = ((chunk ^ r7) << 4) + (((uint32_t)cc & 3u) << 2);
                    asm volatile("st.shared.b32 [%0], %1;" :: "r"(rowaddr + sw), "r"(phw) : "memory");
                    asm volatile("st.shared.b32 [%0], %1;" :: "r"(rowaddr + 16384u + sw), "r"(plw) : "memory");
                }
            }
            MBARRIER_ARRIVE(sb + SO_MBAR + s * 8);   // buf full
            s ^= 1; if (!s) ph ^= 1;
        }
    } else {
        // ======================= CONSUMERS =======================
        int w = wid;
        int mgroup = w >> 2;              // rows [64*mgroup, 64*mgroup+64)
        int ns = (w & 3) * 32;            // n-slice
        uint32_t m = (uint32_t)(lane >> 3);
        uint32_t lr7 = (uint32_t)(lane & 7);
        // A: matrix m -> rows (m&1)*8, k-chunk (m>>1)
        uint32_t a_lane_row = ((m & 1u) << 3) + lr7;
        uint32_t a_cb = m >> 1;
        // B: matrix m -> n (m>>1)*8, k-chunk (m&1)
        uint32_t b_lane_n = ((m >> 1u) << 3) + lr7;
        uint32_t b_cb = m & 1u;
        uint32_t Bhi = sb + SO_B;
        const float4* ep = (const float4*)(smx + SO_EP);
        float2* part = (float2*)(smx + SO_PART);

        int s = 0, ph = 0;
        for (int t = blockIdx.x; t < NT; t += GRID) {
            MBARRIER_WAIT_PARITY(sb + SO_MBAR + s * 8, ph);   // buf full
            uint32_t Ahi = sb + SO_A + (uint32_t)s * 32768u
                         + (((uint32_t)(mgroup * 64) + a_lane_row) << 7);
            int acc1[4][4][4], acc2[4][4][4];
#pragma unroll
            for (int i = 0; i < 4; ++i)
#pragma unroll
                for (int j = 0; j < 4; ++j)
#pragma unroll
                    for (int r = 0; r < 4; ++r) { acc1[i][j][r] = 0; acc2[i][j][r] = 0; }
#pragma unroll
            for (int ks = 0; ks < 4; ++ks) {
                uint32_t bh[8], bl[8];
#pragma unroll
                for (int j = 0; j < 2; ++j) {
                    uint32_t baddr = Bhi + (((uint32_t)(ns + 16 * j) + b_lane_n) << 7)
                                   + ((((uint32_t)(2 * ks) + b_cb) ^ lr7) << 4);
                    LDSM_X4(bh[4 * j], bh[4 * j + 1], bh[4 * j + 2], bh[4 * j + 3], baddr);
                    LDSM_X4(bl[4 * j], bl[4 * j + 1], bl[4 * j + 2], bl[4 * j + 3], baddr + 16384u);
                }
                uint32_t ach = (((uint32_t)(2 * ks) + a_cb) ^ lr7) << 4;
#pragma unroll
                for (int mb = 0; mb < 4; ++mb) {
                    uint32_t aaddr = Ahi + ((uint32_t)mb << 11) + ach;
                    uint32_t ah0, ah1, ah2, ah3, al0, al1, al2, al3;
                    LDSM_X4(ah0, ah1, ah2, ah3, aaddr);
                    LDSM_X4(al0, al1, al2, al3, aaddr + 16384u);
#pragma unroll
                    for (int nb = 0; nb < 4; ++nb) {
                        MMAS8(acc1[mb][nb], ah0, ah1, ah2, ah3, bh[2 * nb], bh[2 * nb + 1]);
                        MMAS8(acc2[mb][nb], ah0, ah1, ah2, ah3, bl[2 * nb], bl[2 * nb + 1]);
                        MMAS8(acc2[mb][nb], al0, al1, al2, al3, bh[2 * nb], bh[2 * nb + 1]);
                    }
                }
            }
            MBARRIER_ARRIVE(sb + SO_MBAR + 16 + s * 8);   // buf free

            // ---- epilogue: scale, relu, dueling heads ----
#pragma unroll
            for (int mb = 0; mb < 4; ++mb) {
                float qp0 = 0.f, av0 = 0.f, qp1 = 0.f, av1 = 0.f;
#pragma unroll
                for (int nb = 0; nb < 4; ++nb) {
                    int c = ns + 8 * nb + 2 * (lane & 3);
                    float4 e0 = ep[c], e1 = ep[c + 1];
                    float C10 = e0.w, C20 = C10 * 0.00390625f;
                    float C11 = e1.w, C21 = C11 * 0.00390625f;
                    float h;
                    h = fmaxf(fmaf(C10, (float)acc1[mb][nb][0], fmaf(C20, (float)acc2[mb][nb][0], e0.x)), 0.f);
                    qp0 += h * e0.y; av0 += h * e0.z;
                    h = fmaxf(fmaf(C11, (float)acc1[mb][nb][1], fmaf(C21, (float)acc2[mb][nb][1], e1.x)), 0.f);
                    qp0 += h * e1.y; av0 += h * e1.z;
                    h = fmaxf(fmaf(C10, (float)acc1[mb][nb][2], fmaf(C20, (float)acc2[mb][nb][2], e0.x)), 0.f);
                    qp1 += h * e0.y; av1 += h * e0.z;
                    h = fmaxf(fmaf(C11, (float)acc1[mb][nb][3], fmaf(C21, (float)acc2[mb][nb][3], e1.x)), 0.f);
                    qp1 += h * e1.y; av1 += h * e1.z;
                }
                qp0 += __shfl_xor_sync(0xffffffffu, qp0, 1); qp0 += __shfl_xor_sync(0xffffffffu, qp0, 2);
                av0 += __shfl_xor_sync(0xffffffffu, av0, 1); av0 += __shfl_xor_sync(0xffffffffu, av0, 2);
                qp1 += __shfl_xor_sync(0xffffffffu, qp1, 1); qp1 += __shfl_xor_sync(0xffffffffu, qp1, 2);
                av1 += __shfl_xor_sync(0xffffffffu, av1, 1); av1 += __shfl_xor_sync(0xffffffffu, av1, 2);
                if ((lane & 3) == 0) {
                    int r0 = mgroup * 64 + mb * 16 + (lane >> 2);
                    part[r0 * 4 + (w & 3)] = make_float2(qp0, av0);
                    part[(r0 + 8) * 4 + (w & 3)] = make_float2(qp1, av1);
                }
            }
            NAMED_BAR(1, 256);
            if (tid < 128) {
                int row = tid;
                const float4* pp = (const float4*)(smx + SO_PART) + row * 2;
                float4 u = pp[0], v = pp[1];
                out[t * TILE_M + row] = u.x + u.z + v.x + v.z + bv0;
                asum += u.y + u.w + v.y + v.w;
            }
            NAMED_BAR(1, 256);
            s ^= 1; if (!s) ph ^= 1;
        }
    }

    __syncthreads();
#pragma unroll
    for (int o = 16; o; o >>= 1) asum += __shfl_xor_sync(0xffffffffu, asum, o);
    float* red = (float*)(smx + SO_PART);
    if (lane == 0) red[wid] = asum;
    __syncthreads();
    if (tid == 0) {
        float sf = 0.f;
#pragma unroll
        for (int i = 0; i < 12; ++i) sf += red[i];
        atomicAdd(&g_sum, (double)sf);
    }
}

// ---------------------------------------------------------------------------
__global__ void finalize_kernel(float* __restrict__ out) {
    int i = blockIdx.x * blockDim.x + threadIdx.x;
    if (i < N_EDGES) {
        float mean = (float)(g_sum * (1.0 / (double)N_EDGES));
        out[i] -= mean;
    }
}

// ---------------------------------------------------------------------------
extern "C" void kernel_launch(void* const* d_in, const int* in_sizes, int n_in,
                              void* d_out, int out_size) {
    const float* node_embs = (const float*)d_in[0];
    const int*   src       = (const int*)d_in[1];
    const int*   dst       = (const int*)d_in[2];
    const float* W1        = (const float*)d_in[3];
    const float* b1        = (const float*)d_in[4];
    const float* W2        = (const float*)d_in[5];
    const float* b2        = (const float*)d_in[6];
    const float* Wv        = (const float*)d_in[7];
    const float* bv        = (const float*)d_in[8];
    const float* Wa        = (const float*)d_in[9];
    // ba (d_in[10]) cancels algebraically
    float* out = (float*)d_out;

    precompute_kernel<<<(N_NODES * 32 + 255) / 256, 256>>>(node_embs, W1, b1);
    prep_w2_kernel<<<H, H>>>(W2);

    cudaFuncSetAttribute(edge_kernel,
                         cudaFuncAttributeMaxDynamicSharedMemorySize, SMEM_TOTAL);
    edge_kernel<<<GRID, NTHREADS, SMEM_TOTAL>>>(src, dst, b2, Wv, bv, Wa, out);

    finalize_kernel<<<(N_EDGES + 255) / 256, 256>>>(out);
}

// round 7
// speedup vs baseline: 1.7753x; 1.0291x over previous
#include <cuda_runtime.h>
#include <cuda_bf16.h>
#include <stdint.h>

#define N_NODES 100000
#define N_EDGES 2000000
#define PER 12
#define H 128
#define TILE_M 128
#define NT (N_EDGES / TILE_M)   // 15625
#define GRID 148
#define NTHREADS 384            // warps 0-7 consumers, 8-11 producers
#define NSTAGES 3

#define SCALE_A (5.0f / 32512.0f)
#define INV_A   (32512.0f / 5.0f)

// ---------------- device scratch (allocation-free rule) ----------------
__device__ float g_P[N_NODES * H];       // node_embs @ W1[:12] + b1
__device__ float g_Q[N_NODES * H];       // node_embs @ W1[12:]
__device__ unsigned char g_B[32768];     // W2^T int8: hi plane 16KB, lo plane 16KB (swizzled)
__device__ float g_C1[H];                // per-col scale
__device__ double g_sum;

// ---------------- helpers ----------------
__device__ __forceinline__ uint32_t smem_to_u32(const void* p) {
    uint32_t a;
    asm("{ .reg .u64 t; cvta.to.shared.u64 t, %1; cvt.u32.u64 %0, t; }" : "=r"(a) : "l"(p));
    return a;
}
#define MBARRIER_INIT(addr, cnt) \
    asm volatile("mbarrier.init.shared.b64 [%0], %1;" :: "r"((uint32_t)(addr)), "r"((uint32_t)(cnt)) : "memory")
#define MBARRIER_ARRIVE(addr) \
    asm volatile("mbarrier.arrive.shared.b64 _, [%0];" :: "r"((uint32_t)(addr)) : "memory")
#define MBARRIER_WAIT_PARITY(addr, par) do { \
    uint32_t _m = (uint32_t)(addr), _p = (uint32_t)(par), _d; \
    asm volatile("{\n\t.reg .pred p;\n\tmbarrier.try_wait.parity.acquire.cta.shared::cta.b64 p, [%1], %2;\n\tselp.b32 %0, 1, 0, p;\n\t}" \
        : "=r"(_d) : "r"(_m), "r"(_p) : "memory"); \
    if (!_d) { \
        asm volatile("{\n\t.reg .pred P1;\n\tWL_%=:\n\tmbarrier.try_wait.parity.acquire.cta.shared::cta.b64 P1, [%0], %1, 0x989680;\n\t@P1 bra.uni WD_%=;\n\tbra.uni WL_%=;\n\tWD_%=:\n\t}" \
            :: "r"(_m), "r"(_p) : "memory"); \
    } } while (0)
#define LDSM_X4(r0, r1, r2, r3, addr) \
    asm volatile("ldmatrix.sync.aligned.m8n8.x4.shared.b16 {%0,%1,%2,%3}, [%4];" \
        : "=r"(r0), "=r"(r1), "=r"(r2), "=r"(r3) : "r"(addr))
#define MMAS8(d, a0, a1, a2, a3, b0, b1) \
    asm volatile("mma.sync.aligned.m16n8k32.row.col.s32.s8.s8.s32 " \
        "{%0,%1,%2,%3}, {%4,%5,%6,%7}, {%8,%9}, {%0,%1,%2,%3};" \
        : "+r"((d)[0]), "+r"((d)[1]), "+r"((d)[2]), "+r"((d)[3]) \
        : "r"(a0), "r"(a1), "r"(a2), "r"(a3), "r"(b0), "r"(b1))
#define PACK_S8(d, v0, v1, v2, v3) \
    asm("{\n\t.reg .b32 t;\n\tcvt.pack.sat.s8.s32.b32 t, %3, %4, %5;\n\t" \
        "cvt.pack.sat.s8.s32.b32 %0, %1, %2, t;\n\t}" \
        : "=r"(d) : "r"(v1), "r"(v0), "r"(v3), "r"(v2), "r"(0))

// ---------------- SMEM layout ----------------
#define SO_MBAR 0        // full[s] @ s*8 ; free[s] @ 24 + s*8
#define SO_EP   1024     // 128 x float4 {b2, Wv+Wa, Wa, C1}
#define SO_RED  3072     // final reduction scratch
#define SO_B    4096     // B hi 16KB, lo 16KB
#define SO_A    36864    // stage s @ +s*32768 : hi 16KB, lo +16384
#define SMEM_TOTAL (36864 + NSTAGES * 32768)

// ---------------------------------------------------------------------------
__global__ void precompute_kernel(const float* __restrict__ E,
                                  const float* __restrict__ W1,
                                  const float* __restrict__ b1) {
    if (blockIdx.x == 0 && threadIdx.x == 0) g_sum = 0.0;
    int warp = (blockIdx.x * blockDim.x + threadIdx.x) >> 5;
    int lane = threadIdx.x & 31;
    if (warp >= N_NODES) return;
    const float* e = E + warp * PER;
    float ek[PER];
#pragma unroll
    for (int k = 0; k < PER; ++k) ek[k] = __ldg(e + k);
    int j = lane << 2;
    float4 p = *(const float4*)(b1 + j);
    float4 q = make_float4(0.f, 0.f, 0.f, 0.f);
#pragma unroll
    for (int k = 0; k < PER; ++k) {
        float4 wa = *(const float4*)(W1 + k * H + j);
        float4 wb = *(const float4*)(W1 + (k + PER) * H + j);
        p.x += ek[k] * wa.x; p.y += ek[k] * wa.y; p.z += ek[k] * wa.z; p.w += ek[k] * wa.w;
        q.x += ek[k] * wb.x; q.y += ek[k] * wb.y; q.z += ek[k] * wb.z; q.w += ek[k] * wb.w;
    }
    *(float4*)(g_P + warp * H + j) = p;
    *(float4*)(g_Q + warp * H + j) = q;
}

// ---------------------------------------------------------------------------
// W2^T per-column 15-bit quantize, hi/lo int8 planes, swizzled [n][k]
// ---------------------------------------------------------------------------
__global__ void prep_w2_kernel(const float* __restrict__ W2) {
    __shared__ float red[4];
    int n = blockIdx.x, k = threadIdx.x;
    float w = W2[k * H + n];
    float m = fabsf(w);
#pragma unroll
    for (int o = 16; o; o >>= 1) m = fmaxf(m, __shfl_xor_sync(0xffffffffu, m, o));
    if ((k & 31) == 0) red[k >> 5] = m;
    __syncthreads();
    float t = fmaxf(fmaxf(red[0], red[1]), fmaxf(red[2], red[3]));
    t = fmaxf(t, 1e-20f);
    int B15 = __float2int_rn(w * (32512.0f / t));
    int hi = (B15 + 128) >> 8;
    int lo = B15 - (hi << 8);
    uint32_t addr = ((uint32_t)n << 7) + ((((uint32_t)(k >> 4)) ^ (uint32_t)(n & 7)) << 4)
                  + ((uint32_t)k & 15u);
    g_B[addr] = (unsigned char)(hi & 255);
    g_B[addr + 16384] = (unsigned char)(lo & 255);
    if (k == 0) g_C1[n] = t * (SCALE_A * 65536.0f / 32512.0f);
}

// ---------------------------------------------------------------------------
// Edge kernel: 3-stage pipeline; row-owning consumers (no cross-warp epilogue)
// ---------------------------------------------------------------------------
extern __shared__ unsigned char smx[];

__global__ void __launch_bounds__(NTHREADS, 1)
edge_kernel(const int* __restrict__ src, const int* __restrict__ dst,
            const float* __restrict__ b2, const float* __restrict__ Wv,
            const float* __restrict__ bv, const float* __restrict__ Wa,
            float* __restrict__ out) {
    uint32_t sb = smem_to_u32(smx);
    int tid = threadIdx.x, wid = tid >> 5, lane = tid & 31;

    if (tid == 0) {
#pragma unroll
        for (int s = 0; s < NSTAGES; ++s) {
            MBARRIER_INIT(sb + SO_MBAR + s * 8, 128);        // full[s]
            MBARRIER_INIT(sb + SO_MBAR + 24 + s * 8, 256);   // free[s]
        }
    }
    if (tid < H) {
        float wa = Wa[tid];
        ((float4*)(smx + SO_EP))[tid] = make_float4(b2[tid], Wv[tid] + wa, wa, g_C1[tid]);
    }
    {   // stage pre-swizzled int8 W2^T (hi+lo planes) into SMEM
        const int4* s1 = (const int4*)g_B;
        int4* d1 = (int4*)(smx + SO_B);
        for (int i = tid; i < 2048; i += NTHREADS) d1[i] = s1[i];
    }
    __syncthreads();
    float bv0 = __ldg(bv);
    float asum = 0.f;

    if (wid >= 8) {
        // ======================= PRODUCERS =======================
        int wbase = (wid - 8) * 32;
        int rr = lane >> 3;
        int cc = lane & 7;
        int s = 0, ph = 1;
        for (int t = blockIdx.x; t < NT; t += GRID) {
            int sidx[8], didx[8];
#pragma unroll
            for (int rg = 0; rg < 8; ++rg) {
                sidx[rg] = __ldg(src + t * TILE_M + wbase + rg * 4 + rr);
                didx[rg] = __ldg(dst + t * TILE_M + wbase + rg * 4 + rr);
            }
            MBARRIER_WAIT_PARITY(sb + SO_MBAR + 24 + s * 8, ph);   // buf free
            uint32_t abase = sb + SO_A + (uint32_t)s * 32768u;
#pragma unroll 2
            for (int rg = 0; rg < 8; ++rg) {
                const float* Pp = g_P + sidx[rg] * H;
                const float* Qp = g_Q + didx[rg] * H;
                int row = wbase + rg * 4 + rr;
                uint32_t rowaddr = abase + ((uint32_t)row << 7);
                uint32_t r7 = (uint32_t)(row & 7);
#pragma unroll
                for (int seg = 0; seg < 4; ++seg) {
                    float4 p = *(const float4*)(Pp + seg * 32 + cc * 4);
                    float4 q = *(const float4*)(Qp + seg * 32 + cc * 4);
                    float h0 = fmaxf(p.x + q.x, 0.f), h1 = fmaxf(p.y + q.y, 0.f);
                    float h2 = fmaxf(p.z + q.z, 0.f), h3 = fmaxf(p.w + q.w, 0.f);
                    int a0 = __float2int_rn(h0 * INV_A), a1 = __float2int_rn(h1 * INV_A);
                    int a2 = __float2int_rn(h2 * INV_A), a3 = __float2int_rn(h3 * INV_A);
                    int hi0 = (a0 + 128) >> 8, hi1 = (a1 + 128) >> 8;
                    int hi2 = (a2 + 128) >> 8, hi3 = (a3 + 128) >> 8;
                    int lo0 = a0 - (hi0 << 8), lo1 = a1 - (hi1 << 8);
                    int lo2 = a2 - (hi2 << 8), lo3 = a3 - (hi3 << 8);
                    uint32_t phw, plw;
                    PACK_S8(phw, hi0, hi1, hi2, hi3);
                    PACK_S8(plw, lo0, lo1, lo2, lo3);
                    uint32_t chunk = (uint32_t)(2 * seg) + ((uint32_t)cc >> 2);
                    uint32_t sw = ((chunk ^ r7) << 4) + (((uint32_t)cc & 3u) << 2);
                    asm volatile("st.shared.b32 [%0], %1;" :: "r"(rowaddr + sw), "r"(phw) : "memory");
                    asm volatile("st.shared.b32 [%0], %1;" :: "r"(rowaddr + 16384u + sw), "r"(plw) : "memory");
                }
            }
            MBARRIER_ARRIVE(sb + SO_MBAR + s * 8);   // buf full
            if (++s == NSTAGES) { s = 0; ph ^= 1; }
        }
    } else {
        // ======================= CONSUMERS (warp owns rows [16w,16w+16)) ===
        int w = wid;
        uint32_t m = (uint32_t)(lane >> 3);
        uint32_t lr7 = (uint32_t)(lane & 7);
        uint32_t a_lane_row = ((m & 1u) << 3) + lr7;
        uint32_t a_cb = m >> 1;
        uint32_t b_lane_n = ((m >> 1u) << 3) + lr7;
        uint32_t b_cb = m & 1u;
        uint32_t Bhi = sb + SO_B;
        const float4* ep = (const float4*)(smx + SO_EP);

        int s = 0, ph = 0;
        for (int t = blockIdx.x; t < NT; t += GRID) {
            MBARRIER_WAIT_PARITY(sb + SO_MBAR + s * 8, ph);   // buf full
            uint32_t Abase = sb + SO_A + (uint32_t)s * 32768u
                           + (((uint32_t)(16 * w) + a_lane_row) << 7);
            float qp0 = 0.f, av0 = 0.f, qp1 = 0.f, av1 = 0.f;
#pragma unroll
            for (int hn = 0; hn < 2; ++hn) {
                int acc1[8][4], acc2[8][4];
#pragma unroll
                for (int i = 0; i < 8; ++i)
#pragma unroll
                    for (int r = 0; r < 4; ++r) { acc1[i][r] = 0; acc2[i][r] = 0; }
#pragma unroll
                for (int ks = 0; ks < 4; ++ks) {
                    uint32_t kssw = (((uint32_t)(2 * ks) + b_cb) ^ lr7) << 4;
                    uint32_t bh[4][4], bl[4][4];
#pragma unroll
                    for (int j = 0; j < 4; ++j) {
                        uint32_t baddr = Bhi + (((uint32_t)(64 * hn + 16 * j) + b_lane_n) << 7) + kssw;
                        LDSM_X4(bh[j][0], bh[j][1], bh[j][2], bh[j][3], baddr);
                        LDSM_X4(bl[j][0], bl[j][1], bl[j][2], bl[j][3], baddr + 16384u);
                    }
                    uint32_t aaddr = Abase + ((((uint32_t)(2 * ks) + a_cb) ^ lr7) << 4);
                    uint32_t ah0, ah1, ah2, ah3, al0, al1, al2, al3;
                    LDSM_X4(ah0, ah1, ah2, ah3, aaddr);
                    LDSM_X4(al0, al1, al2, al3, aaddr + 16384u);
#pragma unroll
                    for (int j = 0; j < 4; ++j) {
                        MMAS8(acc1[2 * j],     ah0, ah1, ah2, ah3, bh[j][0], bh[j][1]);
                        MMAS8(acc1[2 * j + 1], ah0, ah1, ah2, ah3, bh[j][2], bh[j][3]);
                        MMAS8(acc2[2 * j],     ah0, ah1, ah2, ah3, bl[j][0], bl[j][1]);
                        MMAS8(acc2[2 * j + 1], ah0, ah1, ah2, ah3, bl[j][2], bl[j][3]);
                        MMAS8(acc2[2 * j],     al0, al1, al2, al3, bh[j][0], bh[j][1]);
                        MMAS8(acc2[2 * j + 1], al0, al1, al2, al3, bh[j][2], bh[j][3]);
                    }
                }
                // ---- epilogue for this n-half (warp-local) ----
#pragma unroll
                for (int nb = 0; nb < 8; ++nb) {
                    int c = 64 * hn + 8 * nb + 2 * (lane & 3);
                    float4 e0 = ep[c], e1 = ep[c + 1];
                    float C10 = e0.w, C20 = C10 * 0.00390625f;
                    float C11 = e1.w, C21 = C11 * 0.00390625f;
                    float h;
                    h = fmaxf(fmaf(C10, (float)acc1[nb][0], fmaf(C20, (float)acc2[nb][0], e0.x)), 0.f);
                    qp0 += h * e0.y; av0 += h * e0.z;
                    h = fmaxf(fmaf(C11, (float)acc1[nb][1], fmaf(C21, (float)acc2[nb][1], e1.x)), 0.f);
                    qp0 += h * e1.y; av0 += h * e1.z;
                    h = fmaxf(fmaf(C10, (float)acc1[nb][2], fmaf(C20, (float)acc2[nb][2], e0.x)), 0.f);
                    qp1 += h * e0.y; av1 += h * e0.z;
                    h = fmaxf(fmaf(C11, (float)acc1[nb][3], fmaf(C21, (float)acc2[nb][3], e1.x)), 0.f);
                    qp1 += h * e1.y; av1 += h * e1.z;
                }
            }
            MBARRIER_ARRIVE(sb + SO_MBAR + 24 + s * 8);   // buf free (A fully read)

            qp0 += __shfl_xor_sync(0xffffffffu, qp0, 1); qp0 += __shfl_xor_sync(0xffffffffu, qp0, 2);
            av0 += __shfl_xor_sync(0xffffffffu, av0, 1); av0 += __shfl_xor_sync(0xffffffffu, av0, 2);
            qp1 += __shfl_xor_sync(0xffffffffu, qp1, 1); qp1 += __shfl_xor_sync(0xffffffffu, qp1, 2);
            av1 += __shfl_xor_sync(0xffffffffu, av1, 1); av1 += __shfl_xor_sync(0xffffffffu, av1, 2);
            if ((lane & 3) == 0) {
                int row = 16 * w + (lane >> 2);
                out[t * TILE_M + row] = qp0 + bv0;
                out[t * TILE_M + row + 8] = qp1 + bv0;
                asum += av0 + av1;
            }
            if (++s == NSTAGES) { s = 0; ph ^= 1; }
        }
    }

    __syncthreads();
#pragma unroll
    for (int o = 16; o; o >>= 1) asum += __shfl_xor_sync(0xffffffffu, asum, o);
    float* red = (float*)(smx + SO_RED);
    if (lane == 0) red[wid] = asum;
    __syncthreads();
    if (tid == 0) {
        float sf = 0.f;
#pragma unroll
        for (int i = 0; i < 12; ++i) sf += red[i];
        atomicAdd(&g_sum, (double)sf);
    }
}

// ---------------------------------------------------------------------------
__global__ void finalize_kernel(float* __restrict__ out) {
    int i = blockIdx.x * blockDim.x + threadIdx.x;
    if (i < N_EDGES) {
        float mean = (float)(g_sum * (1.0 / (double)N_EDGES));
        out[i] -= mean;
    }
}

// ---------------------------------------------------------------------------
extern "C" void kernel_launch(void* const* d_in, const int* in_sizes, int n_in,
                              void* d_out, int out_size) {
    const float* node_embs = (const float*)d_in[0];
    const int*   src       = (const int*)d_in[1];
    const int*   dst       = (const int*)d_in[2];
    const float* W1        = (const float*)d_in[3];
    const float* b1        = (const float*)d_in[4];
    const float* W2        = (const float*)d_in[5];
    const float* b2        = (const float*)d_in[6];
    const float* Wv        = (const float*)d_in[7];
    const float* bv        = (const float*)d_in[8];
    const float* Wa        = (const float*)d_in[9];
    // ba (d_in[10]) cancels algebraically
    float* out = (float*)d_out;

    precompute_kernel<<<(N_NODES * 32 + 255) / 256, 256>>>(node_embs, W1, b1);
    prep_w2_kernel<<<H, H>>>(W2);

    cudaFuncSetAttribute(edge_kernel,
                         cudaFuncAttributeMaxDynamicSharedMemorySize, SMEM_TOTAL);
    edge_kernel<<<GRID, NTHREADS, SMEM_TOTAL>>>(src, dst, b2, Wv, bv, Wa, out);

    finalize_kernel<<<(N_EDGES + 255) / 256, 256>>>(out);
}

// round 8
// speedup vs baseline: 2.3667x; 1.3332x over previous
#include <cuda_runtime.h>
#include <cuda_bf16.h>
#include <stdint.h>

#define N_NODES 100000
#define N_EDGES 2000000
#define PER 12
#define H 128
#define TILE_M 128
#define NT (N_EDGES / TILE_M)   // 15625
#define GRID 296                // 2 CTAs per SM
#define NTHREADS 256            // 8 warps, all gather+MMA

#define SCALE_A (5.0f / 32512.0f)
#define INV_A   (32512.0f / 5.0f)

// ---------------- device scratch (allocation-free rule) ----------------
__device__ float g_P[N_NODES * H];       // node_embs @ W1[:12] + b1
__device__ float g_Q[N_NODES * H];       // node_embs @ W1[12:]
__device__ unsigned char g_B[32768];     // W2^T int8: hi plane 16KB, lo plane 16KB (swizzled)
__device__ float g_C1[H];                // per-col scale
__device__ double g_sum;

// ---------------- helpers ----------------
__device__ __forceinline__ uint32_t smem_to_u32(const void* p) {
    uint32_t a;
    asm("{ .reg .u64 t; cvta.to.shared.u64 t, %1; cvt.u32.u64 %0, t; }" : "=r"(a) : "l"(p));
    return a;
}
#define LDSM_X4(r0, r1, r2, r3, addr) \
    asm volatile("ldmatrix.sync.aligned.m8n8.x4.shared.b16 {%0,%1,%2,%3}, [%4];" \
        : "=r"(r0), "=r"(r1), "=r"(r2), "=r"(r3) : "r"(addr))
#define MMAS8(d, a0, a1, a2, a3, b0, b1) \
    asm volatile("mma.sync.aligned.m16n8k32.row.col.s32.s8.s8.s32 " \
        "{%0,%1,%2,%3}, {%4,%5,%6,%7}, {%8,%9}, {%0,%1,%2,%3};" \
        : "+r"((d)[0]), "+r"((d)[1]), "+r"((d)[2]), "+r"((d)[3]) \
        : "r"(a0), "r"(a1), "r"(a2), "r"(a3), "r"(b0), "r"(b1))
#define PACK_S8(d, v0, v1, v2, v3) \
    asm("{\n\t.reg .b32 t;\n\tcvt.pack.sat.s8.s32.b32 t, %3, %4, %5;\n\t" \
        "cvt.pack.sat.s8.s32.b32 %0, %1, %2, t;\n\t}" \
        : "=r"(d) : "r"(v1), "r"(v0), "r"(v3), "r"(v2), "r"(0))

// quantize 4 h1 values (p+q, relu) to 15-bit fixed, split int8 hi/lo, pack
__device__ __forceinline__ void quant8(float4 p, float4 q, uint32_t& hi, uint32_t& lo) {
    float h0 = fmaxf(p.x + q.x, 0.f), h1 = fmaxf(p.y + q.y, 0.f);
    float h2 = fmaxf(p.z + q.z, 0.f), h3 = fmaxf(p.w + q.w, 0.f);
    int a0 = __float2int_rn(h0 * INV_A), a1 = __float2int_rn(h1 * INV_A);
    int a2 = __float2int_rn(h2 * INV_A), a3 = __float2int_rn(h3 * INV_A);
    int i0 = (a0 + 128) >> 8, i1 = (a1 + 128) >> 8;
    int i2 = (a2 + 128) >> 8, i3 = (a3 + 128) >> 8;
    int l0 = a0 - (i0 << 8), l1 = a1 - (i1 << 8);
    int l2 = a2 - (i2 << 8), l3 = a3 - (i3 << 8);
    PACK_S8(hi, i0, i1, i2, i3);
    PACK_S8(lo, l0, l1, l2, l3);
}

// ---------------- SMEM layout ----------------
#define SO_EP   0        // 128 x float4 {b2, Wv+Wa, Wa, C1}
#define SO_RED  2048
#define SO_B    4096     // B hi 16KB, lo 16KB
#define SMEM_TOTAL 36864

// ---------------------------------------------------------------------------
__global__ void precompute_kernel(const float* __restrict__ E,
                                  const float* __restrict__ W1,
                                  const float* __restrict__ b1) {
    if (blockIdx.x == 0 && threadIdx.x == 0) g_sum = 0.0;
    int warp = (blockIdx.x * blockDim.x + threadIdx.x) >> 5;
    int lane = threadIdx.x & 31;
    if (warp >= N_NODES) return;
    const float* e = E + warp * PER;
    float ek[PER];
#pragma unroll
    for (int k = 0; k < PER; ++k) ek[k] = __ldg(e + k);
    int j = lane << 2;
    float4 p = *(const float4*)(b1 + j);
    float4 q = make_float4(0.f, 0.f, 0.f, 0.f);
#pragma unroll
    for (int k = 0; k < PER; ++k) {
        float4 wa = *(const float4*)(W1 + k * H + j);
        float4 wb = *(const float4*)(W1 + (k + PER) * H + j);
        p.x += ek[k] * wa.x; p.y += ek[k] * wa.y; p.z += ek[k] * wa.z; p.w += ek[k] * wa.w;
        q.x += ek[k] * wb.x; q.y += ek[k] * wb.y; q.z += ek[k] * wb.z; q.w += ek[k] * wb.w;
    }
    *(float4*)(g_P + warp * H + j) = p;
    *(float4*)(g_Q + warp * H + j) = q;
}

// ---------------------------------------------------------------------------
// W2^T per-column 15-bit quantize, hi/lo int8 planes, swizzled [n][k]
// ---------------------------------------------------------------------------
__global__ void prep_w2_kernel(const float* __restrict__ W2) {
    __shared__ float red[4];
    int n = blockIdx.x, k = threadIdx.x;
    float w = W2[k * H + n];
    float m = fabsf(w);
#pragma unroll
    for (int o = 16; o; o >>= 1) m = fmaxf(m, __shfl_xor_sync(0xffffffffu, m, o));
    if ((k & 31) == 0) red[k >> 5] = m;
    __syncthreads();
    float t = fmaxf(fmaxf(red[0], red[1]), fmaxf(red[2], red[3]));
    t = fmaxf(t, 1e-20f);
    int B15 = __float2int_rn(w * (32512.0f / t));
    int hi = (B15 + 128) >> 8;
    int lo = B15 - (hi << 8);
    uint32_t addr = ((uint32_t)n << 7) + ((((uint32_t)(k >> 4)) ^ (uint32_t)(n & 7)) << 4)
                  + ((uint32_t)k & 15u);
    g_B[addr] = (unsigned char)(hi & 255);
    g_B[addr + 16384] = (unsigned char)(lo & 255);
    if (k == 0) g_C1[n] = t * (SCALE_A * 65536.0f / 32512.0f);
}

// ---------------------------------------------------------------------------
// Edge kernel: no warp specialization, no SMEM A, no sync in steady state.
// Each warp owns rows [16w,16w+16): gathers P/Q directly into MMA A-fragment
// registers (quantize in-lane), runs 192 mma.m16n8k32.s8 per tile with a
// single combined accumulator (acc = (hh<<8) + hl + lh, exact in int32).
// ---------------------------------------------------------------------------
extern __shared__ unsigned char smx[];

__global__ void __launch_bounds__(NTHREADS, 2)
edge_kernel(const int* __restrict__ src, const int* __restrict__ dst,
            const float* __restrict__ b2, const float* __restrict__ Wv,
            const float* __restrict__ bv, const float* __restrict__ Wa,
            float* __restrict__ out) {
    uint32_t sb = smem_to_u32(smx);
    int tid = threadIdx.x, wid = tid >> 5, lane = tid & 31;

    if (tid < H) {
        float wa = Wa[tid];
        ((float4*)(smx + SO_EP))[tid] = make_float4(b2[tid], Wv[tid] + wa, wa, g_C1[tid]);
    }
    {   // stage pre-swizzled int8 W2^T (hi+lo planes) into SMEM
        const int4* s1 = (const int4*)g_B;
        int4* d1 = (int4*)(smx + SO_B);
        for (int i = tid; i < 2048; i += NTHREADS) d1[i] = s1[i];
    }
    __syncthreads();
    float bv0 = __ldg(bv);
    float asum = 0.f;

    int w = wid;
    int row0 = 16 * w + (lane >> 2);           // this lane's first M row
    uint32_t kbase = ((uint32_t)lane & 3u) << 2;
    uint32_t m = (uint32_t)(lane >> 3);
    uint32_t lr7 = (uint32_t)(lane & 7);
    uint32_t b_lane_n = ((m >> 1u) << 3) + lr7;
    uint32_t b_cb = m & 1u;
    uint32_t Bhi = sb + SO_B;
    const float4* ep = (const float4*)(smx + SO_EP);

    for (int t = blockIdx.x; t < NT; t += GRID) {
        // ---- gather indices for the two rows this lane feeds ----
        int s0 = __ldg(src + t * TILE_M + row0);
        int d0 = __ldg(dst + t * TILE_M + row0);
        int s1 = __ldg(src + t * TILE_M + row0 + 8);
        int d1 = __ldg(dst + t * TILE_M + row0 + 8);
        const float* P0 = g_P + s0 * H + kbase;
        const float* Q0 = g_Q + d0 * H + kbase;
        const float* P1 = g_P + s1 * H + kbase;
        const float* Q1 = g_Q + d1 * H + kbase;

        // ---- gather + quantize A fragments in-register ----
        uint32_t Ah[4][4], Al[4][4];   // [ks][a0..a3]
#pragma unroll
        for (int ks = 0; ks < 4; ++ks) {
            int o = ks * 32;
            float4 pa = *(const float4*)(P0 + o);
            float4 qa = *(const float4*)(Q0 + o);
            float4 pb = *(const float4*)(P0 + o + 16);
            float4 qb = *(const float4*)(Q0 + o + 16);
            float4 pc = *(const float4*)(P1 + o);
            float4 qc = *(const float4*)(Q1 + o);
            float4 pd = *(const float4*)(P1 + o + 16);
            float4 qd = *(const float4*)(Q1 + o + 16);
            quant8(pa, qa, Ah[ks][0], Al[ks][0]);   // row0, k+0
            quant8(pc, qc, Ah[ks][1], Al[ks][1]);   // row1, k+0
            quant8(pb, qb, Ah[ks][2], Al[ks][2]);   // row0, k+16
            quant8(pd, qd, Ah[ks][3], Al[ks][3]);   // row1, k+16
        }

        float qp0 = 0.f, av0 = 0.f, qp1 = 0.f, av1 = 0.f;
#pragma unroll
        for (int hn = 0; hn < 2; ++hn) {
            int acc[8][4];
#pragma unroll
            for (int i = 0; i < 8; ++i)
#pragma unroll
                for (int r = 0; r < 4; ++r) acc[i][r] = 0;

            // ---- pass 1: Ahi x Bhi ----
#pragma unroll
            for (int ks = 0; ks < 4; ++ks) {
                uint32_t kssw = (((uint32_t)(2 * ks) + b_cb) ^ lr7) << 4;
#pragma unroll
                for (int j = 0; j < 4; ++j) {
                    uint32_t baddr = Bhi + (((uint32_t)(64 * hn + 16 * j) + b_lane_n) << 7) + kssw;
                    uint32_t h0, h1, h2, h3;
                    LDSM_X4(h0, h1, h2, h3, baddr);
                    MMAS8(acc[2 * j],     Ah[ks][0], Ah[ks][1], Ah[ks][2], Ah[ks][3], h0, h1);
                    MMAS8(acc[2 * j + 1], Ah[ks][0], Ah[ks][1], Ah[ks][2], Ah[ks][3], h2, h3);
                }
            }
            // ---- weight the hh partials by 256 (exact; fits int32) ----
#pragma unroll
            for (int i = 0; i < 8; ++i)
#pragma unroll
                for (int r = 0; r < 4; ++r) acc[i][r] <<= 8;

            // ---- pass 2: Ahi x Blo + Alo x Bhi ----
#pragma unroll
            for (int ks = 0; ks < 4; ++ks) {
                uint32_t kssw = (((uint32_t)(2 * ks) + b_cb) ^ lr7) << 4;
#pragma unroll
                for (int j = 0; j < 4; ++j) {
                    uint32_t baddr = Bhi + (((uint32_t)(64 * hn + 16 * j) + b_lane_n) << 7) + kssw;
                    uint32_t h0, h1, h2, h3, l0, l1, l2, l3;
                    LDSM_X4(h0, h1, h2, h3, baddr);
                    LDSM_X4(l0, l1, l2, l3, baddr + 16384u);
                    MMAS8(acc[2 * j],     Ah[ks][0], Ah[ks][1], Ah[ks][2], Ah[ks][3], l0, l1);
                    MMAS8(acc[2 * j + 1], Ah[ks][0], Ah[ks][1], Ah[ks][2], Ah[ks][3], l2, l3);
                    MMAS8(acc[2 * j],     Al[ks][0], Al[ks][1], Al[ks][2], Al[ks][3], h0, h1);
                    MMAS8(acc[2 * j + 1], Al[ks][0], Al[ks][1], Al[ks][2], Al[ks][3], h2, h3);
                }
            }

            // ---- epilogue for this n-half (warp-local) ----
#pragma unroll
            for (int nb = 0; nb < 8; ++nb) {
                int c = 64 * hn + 8 * nb + 2 * (lane & 3);
                float4 e0 = ep[c], e1 = ep[c + 1];
                float C20 = e0.w * 0.00390625f;
                float C21 = e1.w * 0.00390625f;
                float h;
                h = fmaxf(fmaf(C20, (float)acc[nb][0], e0.x), 0.f); qp0 += h * e0.y; av0 += h * e0.z;
                h = fmaxf(fmaf(C21, (float)acc[nb][1], e1.x), 0.f); qp0 += h * e1.y; av0 += h * e1.z;
                h = fmaxf(fmaf(C20, (float)acc[nb][2], e0.x), 0.f); qp1 += h * e0.y; av1 += h * e0.z;
                h = fmaxf(fmaf(C21, (float)acc[nb][3], e1.x), 0.f); qp1 += h * e1.y; av1 += h * e1.z;
            }
        }

        qp0 += __shfl_xor_sync(0xffffffffu, qp0, 1); qp0 += __shfl_xor_sync(0xffffffffu, qp0, 2);
        av0 += __shfl_xor_sync(0xffffffffu, av0, 1); av0 += __shfl_xor_sync(0xffffffffu, av0, 2);
        qp1 += __shfl_xor_sync(0xffffffffu, qp1, 1); qp1 += __shfl_xor_sync(0xffffffffu, qp1, 2);
        av1 += __shfl_xor_sync(0xffffffffu, av1, 1); av1 += __shfl_xor_sync(0xffffffffu, av1, 2);
        if ((lane & 3) == 0) {
            out[t * TILE_M + row0] = qp0 + bv0;
            out[t * TILE_M + row0 + 8] = qp1 + bv0;
            asum += av0 + av1;
        }
    }

    __syncthreads();
#pragma unroll
    for (int o = 16; o; o >>= 1) asum += __shfl_xor_sync(0xffffffffu, asum, o);
    float* red = (float*)(smx + SO_RED);
    if (lane == 0) red[wid] = asum;
    __syncthreads();
    if (tid == 0) {
        float sf = 0.f;
#pragma unroll
        for (int i = 0; i < 8; ++i) sf += red[i];
        atomicAdd(&g_sum, (double)sf);
    }
}

// ---------------------------------------------------------------------------
__global__ void finalize_kernel(float* __restrict__ out) {
    int i = blockIdx.x * blockDim.x + threadIdx.x;
    if (i < N_EDGES) {
        float mean = (float)(g_sum * (1.0 / (double)N_EDGES));
        out[i] -= mean;
    }
}

// ---------------------------------------------------------------------------
extern "C" void kernel_launch(void* const* d_in, const int* in_sizes, int n_in,
                              void* d_out, int out_size) {
    const float* node_embs = (const float*)d_in[0];
    const int*   src       = (const int*)d_in[1];
    const int*   dst       = (const int*)d_in[2];
    const float* W1        = (const float*)d_in[3];
    const float* b1        = (const float*)d_in[4];
    const float* W2        = (const float*)d_in[5];
    const float* b2        = (const float*)d_in[6];
    const float* Wv        = (const float*)d_in[7];
    const float* bv        = (const float*)d_in[8];
    const float* Wa        = (const float*)d_in[9];
    // ba (d_in[10]) cancels algebraically
    float* out = (float*)d_out;

    precompute_kernel<<<(N_NODES * 32 + 255) / 256, 256>>>(node_embs, W1, b1);
    prep_w2_kernel<<<H, H>>>(W2);

    cudaFuncSetAttribute(edge_kernel,
                         cudaFuncAttributeMaxDynamicSharedMemorySize, SMEM_TOTAL);
    edge_kernel<<<GRID, NTHREADS, SMEM_TOTAL>>>(src, dst, b2, Wv, bv, Wa, out);

    finalize_kernel<<<(N_EDGES + 255) / 256, 256>>>(out);
}

// round 9
// speedup vs baseline: 2.5650x; 1.0838x over previous
#include <cuda_runtime.h>
#include <cuda_bf16.h>
#include <stdint.h>

#define N_NODES 100000
#define N_EDGES 2000000
#define PER 12
#define H 128
#define TILE_M 128
#define NT (N_EDGES / TILE_M)   // 15625
#define GRID 296                // 2 CTAs per SM
#define NTHREADS 256            // 8 warps, all gather+MMA

// P/Q fixed-point: step 2^-13 (max 4.0); A15 = Pint+Qint (max ~28K < 32639)
#define INV_PQ 8192.0f

// ---------------- device scratch (allocation-free rule) ----------------
__device__ short g_Pi[N_NODES * H];      // quantized node_embs @ W1[:12] + b1
__device__ short g_Qi[N_NODES * H];      // quantized node_embs @ W1[12:]
__device__ unsigned char g_B[32768];     // W2^T int8: hi plane 16KB, lo plane 16KB (swizzled)
__device__ float g_C1[H];                // per-col scale
__device__ double g_sum;

// ---------------- helpers ----------------
__device__ __forceinline__ uint32_t smem_to_u32(const void* p) {
    uint32_t a;
    asm("{ .reg .u64 t; cvta.to.shared.u64 t, %1; cvt.u32.u64 %0, t; }" : "=r"(a) : "l"(p));
    return a;
}
#define LDSM_X4(r0, r1, r2, r3, addr) \
    asm volatile("ldmatrix.sync.aligned.m8n8.x4.shared.b16 {%0,%1,%2,%3}, [%4];" \
        : "=r"(r0), "=r"(r1), "=r"(r2), "=r"(r3) : "r"(addr))
#define MMAS8(d, a0, a1, a2, a3, b0, b1) \
    asm volatile("mma.sync.aligned.m16n8k32.row.col.s32.s8.s8.s32 " \
        "{%0,%1,%2,%3}, {%4,%5,%6,%7}, {%8,%9}, {%0,%1,%2,%3};" \
        : "+r"((d)[0]), "+r"((d)[1]), "+r"((d)[2]), "+r"((d)[3]) \
        : "r"(a0), "r"(a1), "r"(a2), "r"(a3), "r"(b0), "r"(b1))
#define PACK_S16(d, vhi, vlo) \
    asm("cvt.pack.sat.s16.s32 %0, %1, %2;" : "=r"(d) : "r"(vhi), "r"(vlo))

// quantize 4 packed-int16 h1 values: relu, split 15-bit -> int8 hi/lo planes.
// p,q each hold int16 lanes (k, k+1) / (k+2, k+3); output byte i = value k+i.
__device__ __forceinline__ void quant4(uint2 p, uint2 q, uint32_t& hi, uint32_t& lo) {
    uint32_t s0 = __vaddss2(p.x, q.x);
    uint32_t s1 = __vaddss2(p.y, q.y);
    s0 = __vmaxs2(s0, 0u);
    s1 = __vmaxs2(s1, 0u);
    s0 += 0x00800080u;                       // +128 per lane (round for hi split)
    s1 += 0x00800080u;
    hi = __byte_perm(s0, s1, 0x7531);        // high bytes: (A+128)>>8 (in [0,127])
    lo = __byte_perm(s0, s1, 0x6420) ^ 0x80808080u;  // low bytes re-biased to s8
}

// ---------------- SMEM layout ----------------
#define SO_EP   0        // 128 x float4 {b2, Wv+Wa, Wa, C1}
#define SO_RED  2048
#define SO_B    4096     // B hi 16KB, lo 16KB
#define SMEM_TOTAL 36864

// ---------------------------------------------------------------------------
// Kernel A: P = E@W1_top + b1 ; Q = E@W1_bot, quantized to int16 step 2^-13.
// ---------------------------------------------------------------------------
__global__ void precompute_kernel(const float* __restrict__ E,
                                  const float* __restrict__ W1,
                                  const float* __restrict__ b1) {
    if (blockIdx.x == 0 && threadIdx.x == 0) g_sum = 0.0;
    int warp = (blockIdx.x * blockDim.x + threadIdx.x) >> 5;
    int lane = threadIdx.x & 31;
    if (warp >= N_NODES) return;
    const float* e = E + warp * PER;
    float ek[PER];
#pragma unroll
    for (int k = 0; k < PER; ++k) ek[k] = __ldg(e + k);
    int j = lane << 2;
    float4 p = *(const float4*)(b1 + j);
    float4 q = make_float4(0.f, 0.f, 0.f, 0.f);
#pragma unroll
    for (int k = 0; k < PER; ++k) {
        float4 wa = *(const float4*)(W1 + k * H + j);
        float4 wb = *(const float4*)(W1 + (k + PER) * H + j);
        p.x += ek[k] * wa.x; p.y += ek[k] * wa.y; p.z += ek[k] * wa.z; p.w += ek[k] * wa.w;
        q.x += ek[k] * wb.x; q.y += ek[k] * wb.y; q.z += ek[k] * wb.z; q.w += ek[k] * wb.w;
    }
    int p0 = __float2int_rn(p.x * INV_PQ), p1 = __float2int_rn(p.y * INV_PQ);
    int p2 = __float2int_rn(p.z * INV_PQ), p3 = __float2int_rn(p.w * INV_PQ);
    int q0 = __float2int_rn(q.x * INV_PQ), q1 = __float2int_rn(q.y * INV_PQ);
    int q2 = __float2int_rn(q.z * INV_PQ), q3 = __float2int_rn(q.w * INV_PQ);
    uint2 wp, wq;
    PACK_S16(wp.x, p1, p0); PACK_S16(wp.y, p3, p2);
    PACK_S16(wq.x, q1, q0); PACK_S16(wq.y, q3, q2);
    *(uint2*)(g_Pi + warp * H + j) = wp;
    *(uint2*)(g_Qi + warp * H + j) = wq;
}

// ---------------------------------------------------------------------------
// W2^T per-column 15-bit quantize, hi/lo int8 planes, swizzled [n][k]
// ---------------------------------------------------------------------------
__global__ void prep_w2_kernel(const float* __restrict__ W2) {
    __shared__ float red[4];
    int n = blockIdx.x, k = threadIdx.x;
    float w = W2[k * H + n];
    float m = fabsf(w);
#pragma unroll
    for (int o = 16; o; o >>= 1) m = fmaxf(m, __shfl_xor_sync(0xffffffffu, m, o));
    if ((k & 31) == 0) red[k >> 5] = m;
    __syncthreads();
    float t = fmaxf(fmaxf(red[0], red[1]), fmaxf(red[2], red[3]));
    t = fmaxf(t, 1e-20f);
    int B15 = __float2int_rn(w * (32512.0f / t));
    int hi = (B15 + 128) >> 8;
    int lo = B15 - (hi << 8);
    uint32_t addr = ((uint32_t)n << 7) + ((((uint32_t)(k >> 4)) ^ (uint32_t)(n & 7)) << 4)
                  + ((uint32_t)k & 15u);
    g_B[addr] = (unsigned char)(hi & 255);
    g_B[addr + 16384] = (unsigned char)(lo & 255);
    // C1 = t * s_A * 65536 / 32512 with s_A = 2^-13
    if (k == 0) g_C1[n] = t * (8.0f / 32512.0f);
}

// ---------------------------------------------------------------------------
// Edge kernel: register-direct int16 gather + SIMD quantize, 192 s8 MMAs/warp
// per tile, combined accumulator acc = (hh<<8) + hl + lh (exact in int32).
// ---------------------------------------------------------------------------
extern __shared__ unsigned char smx[];

__global__ void __launch_bounds__(NTHREADS, 2)
edge_kernel(const int* __restrict__ src, const int* __restrict__ dst,
            const float* __restrict__ b2, const float* __restrict__ Wv,
            const float* __restrict__ bv, const float* __restrict__ Wa,
            float* __restrict__ out) {
    uint32_t sb = smem_to_u32(smx);
    int tid = threadIdx.x, wid = tid >> 5, lane = tid & 31;

    if (tid < H) {
        float wa = Wa[tid];
        ((float4*)(smx + SO_EP))[tid] = make_float4(b2[tid], Wv[tid] + wa, wa, g_C1[tid]);
    }
    {   // stage pre-swizzled int8 W2^T (hi+lo planes) into SMEM
        const int4* s1 = (const int4*)g_B;
        int4* d1 = (int4*)(smx + SO_B);
        for (int i = tid; i < 2048; i += NTHREADS) d1[i] = s1[i];
    }
    __syncthreads();
    float bv0 = __ldg(bv);
    float asum = 0.f;

    int w = wid;
    int row0 = 16 * w + (lane >> 2);           // this lane's first M row
    int kq = lane & 3;                         // uint2 index: shorts 4(lane&3)..+3
    uint32_t m = (uint32_t)(lane >> 3);
    uint32_t lr7 = (uint32_t)(lane & 7);
    uint32_t b_lane_n = ((m >> 1u) << 3) + lr7;
    uint32_t b_cb = m & 1u;
    uint32_t Bhi = sb + SO_B;
    const float4* ep = (const float4*)(smx + SO_EP);

    for (int t = blockIdx.x; t < NT; t += GRID) {
        // ---- gather indices for the two rows this lane feeds ----
        int s0 = __ldg(src + t * TILE_M + row0);
        int d0 = __ldg(dst + t * TILE_M + row0);
        int s1 = __ldg(src + t * TILE_M + row0 + 8);
        int d1 = __ldg(dst + t * TILE_M + row0 + 8);
        const uint2* P0 = (const uint2*)(g_Pi + s0 * H) + kq;
        const uint2* Q0 = (const uint2*)(g_Qi + d0 * H) + kq;
        const uint2* P1 = (const uint2*)(g_Pi + s1 * H) + kq;
        const uint2* Q1 = (const uint2*)(g_Qi + d1 * H) + kq;

        // ---- gather + quantize A fragments in-register (SIMD int16) ----
        uint32_t Ah[4][4], Al[4][4];   // [ks][a0..a3]
#pragma unroll
        for (int ks = 0; ks < 4; ++ks) {
            quant4(P0[ks * 8],     Q0[ks * 8],     Ah[ks][0], Al[ks][0]);   // row0, k+0
            quant4(P1[ks * 8],     Q1[ks * 8],     Ah[ks][1], Al[ks][1]);   // row1, k+0
            quant4(P0[ks * 8 + 4], Q0[ks * 8 + 4], Ah[ks][2], Al[ks][2]);   // row0, k+16
            quant4(P1[ks * 8 + 4], Q1[ks * 8 + 4], Ah[ks][3], Al[ks][3]);   // row1, k+16
        }

        float qp0 = 0.f, av0 = 0.f, qp1 = 0.f, av1 = 0.f;
#pragma unroll
        for (int hn = 0; hn < 2; ++hn) {
            int acc[8][4];
#pragma unroll
            for (int i = 0; i < 8; ++i)
#pragma unroll
                for (int r = 0; r < 4; ++r) acc[i][r] = 0;

            // ---- pass 1: Ahi x Bhi ----
#pragma unroll
            for (int ks = 0; ks < 4; ++ks) {
                uint32_t kssw = (((uint32_t)(2 * ks) + b_cb) ^ lr7) << 4;
#pragma unroll
                for (int j = 0; j < 4; ++j) {
                    uint32_t baddr = Bhi + (((uint32_t)(64 * hn + 16 * j) + b_lane_n) << 7) + kssw;
                    uint32_t h0, h1, h2, h3;
                    LDSM_X4(h0, h1, h2, h3, baddr);
                    MMAS8(acc[2 * j],     Ah[ks][0], Ah[ks][1], Ah[ks][2], Ah[ks][3], h0, h1);
                    MMAS8(acc[2 * j + 1], Ah[ks][0], Ah[ks][1], Ah[ks][2], Ah[ks][3], h2, h3);
                }
            }
            // ---- weight the hh partials by 256 (exact; fits int32) ----
#pragma unroll
            for (int i = 0; i < 8; ++i)
#pragma unroll
                for (int r = 0; r < 4; ++r) acc[i][r] <<= 8;

            // ---- pass 2: Ahi x Blo + Alo x Bhi ----
#pragma unroll
            for (int ks = 0; ks < 4; ++ks) {
                uint32_t kssw = (((uint32_t)(2 * ks) + b_cb) ^ lr7) << 4;
#pragma unroll
                for (int j = 0; j < 4; ++j) {
                    uint32_t baddr = Bhi + (((uint32_t)(64 * hn + 16 * j) + b_lane_n) << 7) + kssw;
                    uint32_t h0, h1, h2, h3, l0, l1, l2, l3;
                    LDSM_X4(h0, h1, h2, h3, baddr);
                    LDSM_X4(l0, l1, l2, l3, baddr + 16384u);
                    MMAS8(acc[2 * j],     Ah[ks][0], Ah[ks][1], Ah[ks][2], Ah[ks][3], l0, l1);
                    MMAS8(acc[2 * j + 1], Ah[ks][0], Ah[ks][1], Ah[ks][2], Ah[ks][3], l2, l3);
                    MMAS8(acc[2 * j],     Al[ks][0], Al[ks][1], Al[ks][2], Al[ks][3], h0, h1);
                    MMAS8(acc[2 * j + 1], Al[ks][0], Al[ks][1], Al[ks][2], Al[ks][3], h2, h3);
                }
            }

            // ---- epilogue for this n-half (warp-local) ----
#pragma unroll
            for (int nb = 0; nb < 8; ++nb) {
                int c = 64 * hn + 8 * nb + 2 * (lane & 3);
                float4 e0 = ep[c], e1 = ep[c + 1];
                float C20 = e0.w * 0.00390625f;
                float C21 = e1.w * 0.00390625f;
                float h;
                h = fmaxf(fmaf(C20, (float)acc[nb][0], e0.x), 0.f); qp0 += h * e0.y; av0 += h * e0.z;
                h = fmaxf(fmaf(C21, (float)acc[nb][1], e1.x), 0.f); qp0 += h * e1.y; av0 += h * e1.z;
                h = fmaxf(fmaf(C20, (float)acc[nb][2], e0.x), 0.f); qp1 += h * e0.y; av1 += h * e0.z;
                h = fmaxf(fmaf(C21, (float)acc[nb][3], e1.x), 0.f); qp1 += h * e1.y; av1 += h * e1.z;
            }
        }

        qp0 += __shfl_xor_sync(0xffffffffu, qp0, 1); qp0 += __shfl_xor_sync(0xffffffffu, qp0, 2);
        av0 += __shfl_xor_sync(0xffffffffu, av0, 1); av0 += __shfl_xor_sync(0xffffffffu, av0, 2);
        qp1 += __shfl_xor_sync(0xffffffffu, qp1, 1); qp1 += __shfl_xor_sync(0xffffffffu, qp1, 2);
        av1 += __shfl_xor_sync(0xffffffffu, av1, 1); av1 += __shfl_xor_sync(0xffffffffu, av1, 2);
        if ((lane & 3) == 0) {
            out[t * TILE_M + row0] = qp0 + bv0;
            out[t * TILE_M + row0 + 8] = qp1 + bv0;
            asum += av0 + av1;
        }
    }

    __syncthreads();
#pragma unroll
    for (int o = 16; o; o >>= 1) asum += __shfl_xor_sync(0xffffffffu, asum, o);
    float* red = (float*)(smx + SO_RED);
    if (lane == 0) red[wid] = asum;
    __syncthreads();
    if (tid == 0) {
        float sf = 0.f;
#pragma unroll
        for (int i = 0; i < 8; ++i) sf += red[i];
        atomicAdd(&g_sum, (double)sf);
    }
}

// ---------------------------------------------------------------------------
__global__ void finalize_kernel(float* __restrict__ out) {
    int i = blockIdx.x * blockDim.x + threadIdx.x;
    if (i < N_EDGES) {
        float mean = (float)(g_sum * (1.0 / (double)N_EDGES));
        out[i] -= mean;
    }
}

// ---------------------------------------------------------------------------
extern "C" void kernel_launch(void* const* d_in, const int* in_sizes, int n_in,
                              void* d_out, int out_size) {
    const float* node_embs = (const float*)d_in[0];
    const int*   src       = (const int*)d_in[1];
    const int*   dst       = (const int*)d_in[2];
    const float* W1        = (const float*)d_in[3];
    const float* b1        = (const float*)d_in[4];
    const float* W2        = (const float*)d_in[5];
    const float* b2        = (const float*)d_in[6];
    const float* Wv        = (const float*)d_in[7];
    const float* bv        = (const float*)d_in[8];
    const float* Wa        = (const float*)d_in[9];
    // ba (d_in[10]) cancels algebraically
    float* out = (float*)d_out;

    precompute_kernel<<<(N_NODES * 32 + 255) / 256, 256>>>(node_embs, W1, b1);
    prep_w2_kernel<<<H, H>>>(W2);

    cudaFuncSetAttribute(edge_kernel,
                         cudaFuncAttributeMaxDynamicSharedMemorySize, SMEM_TOTAL);
    edge_kernel<<<GRID, NTHREADS, SMEM_TOTAL>>>(src, dst, b2, Wv, bv, Wa, out);

    finalize_kernel<<<(N_EDGES + 255) / 256, 256>>>(out);
}